// round 1
// baseline (speedup 1.0000x reference)
#include <cuda_runtime.h>
#include <cstddef>

// Problem constants (from reference setup_inputs)
constexpr int B    = 4;
constexpr int NS   = 512;     // n_support
constexpr int NQ   = 4096;    // n_query
constexpr int D    = 128;
constexpr int NTOT = NS + NQ; // 4608

constexpr float TAU_C = 0.1f;
constexpr float A2    = 0.9f;   // ALPHA_2
// Key identity: einsum('bij,bid->bid', attn, q) = q * rowsum(attn) = q,
// so new_query == query (to ~1e-6) and the huge q-q attention is skipped.

// Scratch: ||q||^2 per (b, q). 64 KB. (__device__ global => no allocation.)
__device__ float g_qnorm[B * NQ];

// ---------------------------------------------------------------------------
// Kernel 1: copy query rows to output and compute query squared norms.
// One warp per query row (128 floats = 32 lanes x float4).
// ---------------------------------------------------------------------------
__global__ void __launch_bounds__(256) prep_kernel(const float* __restrict__ feat,
                                                   float* __restrict__ out)
{
    int gwarp = (blockIdx.x * blockDim.x + threadIdx.x) >> 5;
    int lane  = threadIdx.x & 31;
    if (gwarp >= B * NQ) return;
    int b = gwarp / NQ;
    int q = gwarp - b * NQ;

    size_t row = (size_t)b * NTOT + NS + q;
    const float4* src = (const float4*)(feat + row * D);
    float4*       dst = (float4*)(out + row * D);

    float4 v = src[lane];
    dst[lane] = v;

    float ss = v.x * v.x + v.y * v.y + v.z * v.z + v.w * v.w;
    #pragma unroll
    for (int o = 16; o > 0; o >>= 1)
        ss += __shfl_xor_sync(0xffffffffu, ss, o);
    if (lane == 0) g_qnorm[gwarp] = ss;
}

// ---------------------------------------------------------------------------
// Kernel 2: new_support = 0.1*support + 0.9 * softmax(-TAU*sqdist(s,q)) @ q
// Grid: 4 batches x 32 blocks of SB=16 support rows = 128 CTAs.
// CTA: 256 threads = 8 warps; each warp owns 2 support rows.
// Query streamed in tiles of QT=32 rows through padded smem.
// Softmax uses shifted logits l = TAU*(2 s.q - ||q||^2); the -TAU*||s||^2
// term is a per-row constant and cancels. l in ~[-35,+8] -> expf safe, no
// running max needed.
// ---------------------------------------------------------------------------
constexpr int SB      = 16;   // support rows per CTA
constexpr int QT      = 32;   // query rows per smem tile
constexpr int QSTRIDE = 132;  // padded row stride (floats) -> conflict-free LDS.128

__global__ void __launch_bounds__(256, 1) support_kernel(const float* __restrict__ feat,
                                                         float* __restrict__ out)
{
    __shared__ float ssm[SB * D];            // support rows
    __shared__ float qsm[QT * QSTRIDE];      // query tile (padded)
    __shared__ float qnsm[QT];               // query norms for tile

    const int b     = blockIdx.x >> 5;       // 32 support-blocks per batch
    const int sblk  = blockIdx.x & 31;
    const int sbase = sblk * SB;
    const int tid   = threadIdx.x;
    const int lane  = tid & 31;
    const int warp  = tid >> 5;

    // Load this CTA's 16 support rows into smem (512 float4, 2 per thread).
    {
        const float4* sp = (const float4*)(feat + ((size_t)b * NTOT + sbase) * D);
        #pragma unroll
        for (int i = tid; i < SB * D / 4; i += 256)
            ((float4*)ssm)[i] = sp[i];
    }

    const float* s0 = ssm + (2 * warp) * D;
    const float* s1 = s0 + D;

    float4 acc0 = make_float4(0.f, 0.f, 0.f, 0.f);
    float4 acc1 = make_float4(0.f, 0.f, 0.f, 0.f);
    float den0 = 0.f, den1 = 0.f;

    const float* qbase  = feat + ((size_t)b * NTOT + NS) * D;
    const float* qnbase = g_qnorm + b * NQ;

    for (int tile = 0; tile < NQ / QT; ++tile) {
        __syncthreads();  // previous tile fully consumed
        // Load query tile: QT*D = 4096 floats = 1024 float4; 4 per thread.
        {
            const float4* g = (const float4*)(qbase + (size_t)tile * QT * D);
            #pragma unroll
            for (int i = 0; i < 4; ++i) {
                int idx = tid + i * 256;      // float4 index within tile
                int row = idx >> 5;           // D/4 = 32 float4 per row
                int c4  = idx & 31;
                *(float4*)&qsm[row * QSTRIDE + c4 * 4] = g[idx];
            }
            if (tid < QT) qnsm[tid] = qnbase[tile * QT + tid];
        }
        __syncthreads();

        // ---- logits: each lane computes s0.q and s1.q for q = tile*32+lane
        float dot0 = 0.f, dot1 = 0.f;
        #pragma unroll
        for (int k4 = 0; k4 < D / 4; ++k4) {
            float4 q  = *(const float4*)&qsm[lane * QSTRIDE + k4 * 4];
            float4 a0 = *(const float4*)&s0[k4 * 4];   // broadcast
            float4 a1 = *(const float4*)&s1[k4 * 4];   // broadcast
            dot0 += a0.x * q.x; dot0 += a0.y * q.y;
            dot0 += a0.z * q.z; dot0 += a0.w * q.w;
            dot1 += a1.x * q.x; dot1 += a1.y * q.y;
            dot1 += a1.z * q.z; dot1 += a1.w * q.w;
        }
        const float qn = qnsm[lane];
        const float w0 = __expf(TAU_C * (2.f * dot0 - qn));
        const float w1 = __expf(TAU_C * (2.f * dot1 - qn));
        den0 += w0;
        den1 += w1;

        // ---- AV accumulation: acc[d] += w_q * q[d], d = 4*lane..4*lane+3
        #pragma unroll
        for (int qq = 0; qq < QT; ++qq) {
            float u0 = __shfl_sync(0xffffffffu, w0, qq);
            float u1 = __shfl_sync(0xffffffffu, w1, qq);
            float4 q = *(const float4*)&qsm[qq * QSTRIDE + lane * 4];
            acc0.x += u0 * q.x; acc0.y += u0 * q.y;
            acc0.z += u0 * q.z; acc0.w += u0 * q.w;
            acc1.x += u1 * q.x; acc1.y += u1 * q.y;
            acc1.z += u1 * q.z; acc1.w += u1 * q.w;
        }
    }

    // Reduce denominators across lanes (each lane summed its own q's).
    #pragma unroll
    for (int o = 16; o > 0; o >>= 1) {
        den0 += __shfl_xor_sync(0xffffffffu, den0, o);
        den1 += __shfl_xor_sync(0xffffffffu, den1, o);
    }
    const float r0 = A2 / den0;
    const float r1 = A2 / den1;

    // Output: out_row = 0.1 * support + 0.9 * acc / den
    const float4 sv0 = *(const float4*)&s0[lane * 4];
    const float4 sv1 = *(const float4*)&s1[lane * 4];

    float4 o0, o1;
    o0.x = 0.1f * sv0.x + r0 * acc0.x;
    o0.y = 0.1f * sv0.y + r0 * acc0.y;
    o0.z = 0.1f * sv0.z + r0 * acc0.z;
    o0.w = 0.1f * sv0.w + r0 * acc0.w;
    o1.x = 0.1f * sv1.x + r1 * acc1.x;
    o1.y = 0.1f * sv1.y + r1 * acc1.y;
    o1.z = 0.1f * sv1.z + r1 * acc1.z;
    o1.w = 0.1f * sv1.w + r1 * acc1.w;

    float4* out0 = (float4*)(out + ((size_t)b * NTOT + sbase + 2 * warp) * D);
    float4* out1 = (float4*)(out + ((size_t)b * NTOT + sbase + 2 * warp + 1) * D);
    out0[lane] = o0;
    out1[lane] = o1;
}

// ---------------------------------------------------------------------------
extern "C" void kernel_launch(void* const* d_in, const int* in_sizes, int n_in,
                              void* d_out, int out_size)
{
    const float* feat = (const float*)d_in[0];   // (4, 4608, 128) fp32
    // d_in[1]: support_labels (int64) — unused by the math.
    float* out = (float*)d_out;                  // (4, 4608, 128) fp32

    // Kernel 1: 16384 query rows, one warp each -> 2048 CTAs of 256.
    prep_kernel<<<(B * NQ * 32 + 255) / 256, 256>>>(feat, out);
    // Kernel 2: 4 batches * 32 blocks of 16 support rows = 128 CTAs.
    support_kernel<<<B * (NS / SB), 256>>>(feat, out);
}

// round 3
// speedup vs baseline: 11.1097x; 11.1097x over previous
#include <cuda_runtime.h>
#include <cuda_bf16.h>
#include <cstdint>
#include <cstddef>

// ---------------------------------------------------------------- constants
constexpr int B      = 4;
constexpr int NS     = 512;
constexpr int NQ     = 4096;
constexpr int D      = 128;
constexpr int NTOT   = NS + NQ;        // 4608
constexpr int NSPLIT = 8;              // query splits per support tile
constexpr int QSPL   = NQ / NSPLIT;    // 512 q per CTA
constexpr int SUBQ   = 64;             // q subtile
constexpr int NSUB   = QSPL / SUBQ;    // 8
constexpr int STILES = NS / 128;       // 4

constexpr int ROWB   = 272;            // smem row stride bytes (256 data + 16 pad)

// smem layout (dynamic)
constexpr int SM_S    = 0;                       // 128 x 272
constexpr int SM_Q0   = SM_S  + 128 * ROWB;      // 64 x 272
constexpr int SM_Q1   = SM_Q0 + 64 * ROWB;
constexpr int SM_QN0  = SM_Q1 + 64 * ROWB;       // 64 floats
constexpr int SM_QN1  = SM_QN0 + 256;
constexpr int SMEM_BYTES = SM_QN1 + 256;         // 70,656 B

// scratch (device globals: no allocation)
__device__ __nv_bfloat16 g_fbf16[(size_t)B * NTOT * D];                  // 4.7 MB
__device__ float g_qnorm[B * NQ];
__device__ float g_rpart[(size_t)B * STILES * NSPLIT * 128 * 128];       // 8.4 MB
__device__ float g_den[B * STILES * NSPLIT * 128];

// ---------------------------------------------------------------- helpers
__device__ __forceinline__ uint32_t smem_u32(const void* p) {
    uint32_t a;
    asm("{ .reg .u64 t; cvta.to.shared.u64 t, %1; cvt.u32.u64 %0, t; }"
        : "=r"(a) : "l"(p));
    return a;
}
__device__ __forceinline__ void cp16(uint32_t dst, const void* src) {
    asm volatile("cp.async.ca.shared.global [%0], [%1], 16;" :: "r"(dst), "l"(src));
}
#define CP_COMMIT() asm volatile("cp.async.commit_group;" ::: "memory")
#define CP_WAIT0()  asm volatile("cp.async.wait_group 0;" ::: "memory")

#define LDSM4(r0, r1, r2, r3, a) \
    asm volatile("ldmatrix.sync.aligned.m8n8.x4.shared.b16 {%0,%1,%2,%3}, [%4];" \
        : "=r"(r0), "=r"(r1), "=r"(r2), "=r"(r3) : "r"(a))
#define LDSM4T(r0, r1, r2, r3, a) \
    asm volatile("ldmatrix.sync.aligned.m8n8.x4.trans.shared.b16 {%0,%1,%2,%3}, [%4];" \
        : "=r"(r0), "=r"(r1), "=r"(r2), "=r"(r3) : "r"(a))

#define MMA16816(d, a, b0, b1) \
    asm volatile("mma.sync.aligned.m16n8k16.row.col.f32.bf16.bf16.f32 " \
        "{%0,%1,%2,%3}, {%4,%5,%6,%7}, {%8,%9}, {%0,%1,%2,%3};" \
        : "+f"((d)[0]), "+f"((d)[1]), "+f"((d)[2]), "+f"((d)[3]) \
        : "r"((a)[0]), "r"((a)[1]), "r"((a)[2]), "r"((a)[3]), "r"(b0), "r"(b1))

// ---------------------------------------------------------------- kernel 1: prep
// One warp per feature row: write bf16 copy; for query rows also copy to out
// and compute ||q||^2.
__global__ void __launch_bounds__(256) prep_kernel(const float* __restrict__ feat,
                                                   float* __restrict__ out)
{
    int gwarp = (blockIdx.x * blockDim.x + threadIdx.x) >> 5;
    int lane  = threadIdx.x & 31;
    if (gwarp >= B * NTOT) return;
    int b = gwarp / NTOT;
    int n = gwarp - b * NTOT;

    size_t row = (size_t)b * NTOT + n;
    float4 v = ((const float4*)(feat + row * D))[lane];

    __nv_bfloat162 lo = __floats2bfloat162_rn(v.x, v.y);
    __nv_bfloat162 hi = __floats2bfloat162_rn(v.z, v.w);
    uint2 u;
    u.x = *(uint32_t*)&lo;
    u.y = *(uint32_t*)&hi;
    ((uint2*)(g_fbf16 + row * D))[lane] = u;

    if (n >= NS) {
        ((float4*)(out + row * D))[lane] = v;
        float ss = v.x*v.x + v.y*v.y + v.z*v.z + v.w*v.w;
        #pragma unroll
        for (int o = 16; o > 0; o >>= 1) ss += __shfl_xor_sync(0xffffffffu, ss, o);
        if (lane == 0) g_qnorm[b * NQ + (n - NS)] = ss;
    }
}

// ---------------------------------------------------------------- kernel 2: attention
__global__ void __launch_bounds__(256, 1) attn_kernel()
{
    extern __shared__ char smem[];
    const int bid   = blockIdx.x;
    const int split = bid & 7;
    const int stile = (bid >> 3) & 3;
    const int b     = bid >> 5;
    const int tid   = threadIdx.x;
    const int wid   = tid >> 5;
    const int lane  = tid & 31;
    const uint32_t sb = smem_u32(smem);

    const char* Sg = (const char*)(g_fbf16 + ((size_t)b * NTOT + (size_t)stile * 128) * D);
    const char* Qg = (const char*)(g_fbf16 + ((size_t)b * NTOT + NS + (size_t)split * QSPL) * D);
    const float* qn_g = g_qnorm + b * NQ + split * QSPL;

    // ---- issue S tile (128 rows) + Q subtile 0 as one cp.async group
    #pragma unroll
    for (int i = 0; i < 8; ++i) {
        int c = tid + i * 256;                 // 0..2047
        int r = c >> 4, j = c & 15;
        cp16(sb + SM_S + r * ROWB + j * 16, Sg + r * 256 + j * 16);
    }
    #pragma unroll
    for (int i = 0; i < 4; ++i) {
        int c = tid + i * 256;                 // 0..1023
        int r = c >> 4, j = c & 15;
        cp16(sb + SM_Q0 + r * ROWB + j * 16, Qg + r * 256 + j * 16);
    }
    CP_COMMIT();
    if (tid < SUBQ) ((float*)(smem + SM_QN0))[tid] = qn_g[tid];

    CP_WAIT0();
    __syncthreads();

    // ---- load S A-fragments once: A[k][0..3], k = 8 steps of 16 d
    uint32_t A[8][4];
    {
        uint32_t arow = sb + SM_S + (16 * wid + (lane & 15)) * ROWB + ((lane >> 4) << 4);
        #pragma unroll
        for (int k = 0; k < 8; ++k)
            LDSM4(A[k][0], A[k][1], A[k][2], A[k][3], arow + k * 32);
    }

    float acc2[16][4];
    #pragma unroll
    for (int g = 0; g < 16; ++g)
        #pragma unroll
        for (int j = 0; j < 4; ++j) acc2[g][j] = 0.f;
    float den0 = 0.f, den1 = 0.f;

    for (int t = 0; t < NSUB; ++t) {
        const uint32_t qb  = sb + ((t & 1) ? SM_Q1 : SM_Q0);
        const float* qn_s  = (const float*)(smem + ((t & 1) ? SM_QN1 : SM_QN0));

        // prefetch next subtile
        if (t + 1 < NSUB) {
            const char* src = Qg + (size_t)(t + 1) * SUBQ * 256;
            uint32_t dst = sb + (((t + 1) & 1) ? SM_Q1 : SM_Q0);
            #pragma unroll
            for (int i = 0; i < 4; ++i) {
                int c = tid + i * 256;
                int r = c >> 4, j = c & 15;
                cp16(dst + r * ROWB + j * 16, src + r * 256 + j * 16);
            }
            CP_COMMIT();
            if (tid < SUBQ)
                ((float*)(smem + (((t + 1) & 1) ? SM_QN1 : SM_QN0)))[tid] =
                    qn_g[(t + 1) * SUBQ + tid];
        }

        // ---- GEMM1: logits c1[8 n-tiles][4] = S . Q^T (K = 128 d)
        float c1[8][4];
        #pragma unroll
        for (int g = 0; g < 8; ++g)
            #pragma unroll
            for (int j = 0; j < 4; ++j) c1[g][j] = 0.f;

        {
            // B address: rows = q, cols = d
            uint32_t baddr = qb + ((lane & 7) + ((lane >> 4) << 3)) * ROWB
                                + (((lane >> 3) & 1) << 4);
            #pragma unroll
            for (int g = 0; g < 4; ++g) {          // n16 groups over 64 q
                #pragma unroll
                for (int k = 0; k < 8; ++k) {      // k16 over 128 d
                    uint32_t b0, b1, b2, b3;
                    LDSM4(b0, b1, b2, b3, baddr + g * 16 * ROWB + k * 32);
                    MMA16816(c1[g * 2],     A[k], b0, b1);
                    MMA16816(c1[g * 2 + 1], A[k], b2, b3);
                }
            }
        }

        // ---- epilogue: w = exp(0.2*dot - 0.1*||q||^2), pack GEMM2 A frags
        uint32_t W[4][4];
        #pragma unroll
        for (int g = 0; g < 8; ++g) {
            int q0 = g * 8 + (lane & 3) * 2;
            float qa = qn_s[q0], qc = qn_s[q0 + 1];
            float w00 = __expf(0.2f * c1[g][0] - 0.1f * qa);
            float w01 = __expf(0.2f * c1[g][1] - 0.1f * qc);
            float w10 = __expf(0.2f * c1[g][2] - 0.1f * qa);
            float w11 = __expf(0.2f * c1[g][3] - 0.1f * qc);
            den0 += w00 + w01;
            den1 += w10 + w11;
            uint32_t p0, p1;
            asm("cvt.rn.satfinite.bf16x2.f32 %0, %1, %2;" : "=r"(p0) : "f"(w01), "f"(w00));
            asm("cvt.rn.satfinite.bf16x2.f32 %0, %1, %2;" : "=r"(p1) : "f"(w11), "f"(w10));
            int kk = g >> 1, h = g & 1;
            W[kk][h * 2 + 0] = p0;
            W[kk][h * 2 + 1] = p1;
        }

        // ---- GEMM2: acc2 += W . Q  (K = 64 q, N = 128 d), B = ldmatrix.trans
        {
            uint32_t baddr = qb + ((lane & 7) + (((lane >> 3) & 1) << 3)) * ROWB
                                + ((lane >> 4) << 4);
            #pragma unroll
            for (int g = 0; g < 8; ++g) {          // n16 over 128 d
                #pragma unroll
                for (int kk = 0; kk < 4; ++kk) {   // k16 over 64 q
                    uint32_t b0, b1, b2, b3;
                    LDSM4T(b0, b1, b2, b3, baddr + kk * 16 * ROWB + g * 32);
                    MMA16816(acc2[g * 2],     W[kk], b0, b1);
                    MMA16816(acc2[g * 2 + 1], W[kk], b2, b3);
                }
            }
        }

        if (t + 1 < NSUB) {
            CP_WAIT0();
            __syncthreads();
        }
    }

    // ---- write partials
    const int rbase = ((b * STILES + stile) * NSPLIT + split) * 128;
    const int r0 = 16 * wid + (lane >> 2);
    float* rp0 = g_rpart + (size_t)(rbase + r0) * 128;
    float* rp1 = g_rpart + (size_t)(rbase + r0 + 8) * 128;
    #pragma unroll
    for (int g = 0; g < 16; ++g) {
        int dc = g * 8 + (lane & 3) * 2;
        *(float2*)(rp0 + dc) = make_float2(acc2[g][0], acc2[g][1]);
        *(float2*)(rp1 + dc) = make_float2(acc2[g][2], acc2[g][3]);
    }
    den0 += __shfl_xor_sync(0xffffffffu, den0, 1);
    den0 += __shfl_xor_sync(0xffffffffu, den0, 2);
    den1 += __shfl_xor_sync(0xffffffffu, den1, 1);
    den1 += __shfl_xor_sync(0xffffffffu, den1, 2);
    if ((lane & 3) == 0) {
        g_den[rbase + r0]     = den0;
        g_den[rbase + r0 + 8] = den1;
    }
}

// ---------------------------------------------------------------- kernel 3: combine
__global__ void __launch_bounds__(256) combine_kernel(const float* __restrict__ feat,
                                                      float* __restrict__ out)
{
    int gw   = (blockIdx.x * blockDim.x + threadIdx.x) >> 5;
    int lane = threadIdx.x & 31;
    if (gw >= B * NS) return;
    int b = gw >> 9;
    int s = gw & 511;
    int stile = s >> 7, r = s & 127;

    float4 acc = make_float4(0.f, 0.f, 0.f, 0.f);
    float den = 0.f;
    #pragma unroll
    for (int p = 0; p < NSPLIT; ++p) {
        size_t base = ((size_t)(b * STILES + stile) * NSPLIT + p) * 128 + r;
        float4 v = ((const float4*)(g_rpart + base * 128))[lane];
        acc.x += v.x; acc.y += v.y; acc.z += v.z; acc.w += v.w;
        den += g_den[base];
    }
    float inv = 0.9f / den;
    const float4 sv = ((const float4*)(feat + ((size_t)b * NTOT + s) * D))[lane];
    float4 o;
    o.x = 0.1f * sv.x + inv * acc.x;
    o.y = 0.1f * sv.y + inv * acc.y;
    o.z = 0.1f * sv.z + inv * acc.z;
    o.w = 0.1f * sv.w + inv * acc.w;
    ((float4*)(out + ((size_t)b * NTOT + s) * D))[lane] = o;
}

// ---------------------------------------------------------------- launch
extern "C" void kernel_launch(void* const* d_in, const int* in_sizes, int n_in,
                              void* d_out, int out_size)
{
    const float* feat = (const float*)d_in[0];   // (4, 4608, 128) fp32
    float* out = (float*)d_out;

    cudaFuncSetAttribute(attn_kernel, cudaFuncAttributeMaxDynamicSharedMemorySize,
                         SMEM_BYTES);

    prep_kernel<<<(B * NTOT * 32 + 255) / 256, 256>>>(feat, out);
    attn_kernel<<<B * STILES * NSPLIT, 256, SMEM_BYTES>>>();
    combine_kernel<<<(B * NS * 32 + 255) / 256, 256>>>(feat, out);
}